// round 2
// baseline (speedup 1.0000x reference)
#include <cuda_runtime.h>
#include <stdint.h>

// Output nodes = N_NODES / 3 = 1,000,000
#define MAX_OUT_NODES 1000000
__device__ float g_agg[MAX_OUT_NODES];

// ---------------------------------------------------------------------------
// Kernel 1: zero the aggregation scratch (vectorized)
// ---------------------------------------------------------------------------
__global__ void zero_agg_kernel(int m4) {
    int i = blockIdx.x * blockDim.x + threadIdx.x;
    if (i < m4) reinterpret_cast<float4*>(g_agg)[i] = make_float4(0.f, 0.f, 0.f, 0.f);
}

// ---------------------------------------------------------------------------
// Kernel 2: edge scatter. edge_index is int32 (harness downcasts int64).
// Only edges with dst % 3 == 0 contribute to the output (h is subsampled at
// stride 3 before the MLP) -> skip gather + atomic for 2/3 of edges.
// dst row read as int4 (4 edges / 16B load); src loaded scalar, predicated.
// ---------------------------------------------------------------------------
__global__ void scatter_kernel(const int* __restrict__ src,
                               const int* __restrict__ dst,
                               const float* __restrict__ x,
                               int nedges) {
    const int4* dst4 = reinterpret_cast<const int4*>(dst);
    int q = blockIdx.x * blockDim.x + threadIdx.x;  // quad index (4 edges)
    int nquads = nedges >> 2;

    if (q < nquads) {
        int4 d = __ldg(&dst4[q]);
        int e = 4 * q;

        if (d.x % 3 == 0) {
            int s = __ldg(&src[e + 0]);
            atomicAdd(&g_agg[d.x / 3], __ldg(&x[s]));
        }
        if (d.y % 3 == 0) {
            int s = __ldg(&src[e + 1]);
            atomicAdd(&g_agg[d.y / 3], __ldg(&x[s]));
        }
        if (d.z % 3 == 0) {
            int s = __ldg(&src[e + 2]);
            atomicAdd(&g_agg[d.z / 3], __ldg(&x[s]));
        }
        if (d.w % 3 == 0) {
            int s = __ldg(&src[e + 3]);
            atomicAdd(&g_agg[d.w / 3], __ldg(&x[s]));
        }
    }

    // Tail (nedges not a multiple of 4)
    int tail_start = nquads << 2;
    int t = tail_start + q;
    if (q < 4 && t < nedges) {
        int dd = __ldg(&dst[t]);
        if (dd % 3 == 0) {
            int s = __ldg(&src[t]);
            atomicAdd(&g_agg[dd / 3], __ldg(&x[s]));
        }
    }
}

// ---------------------------------------------------------------------------
// Kernel 3: finalize. h = agg*Wl + x[3i]*Wr, then MLP(1->2->relu->1).
// ---------------------------------------------------------------------------
__global__ void finalize_kernel(const float* __restrict__ x,
                                const float* __restrict__ Wl,
                                const float* __restrict__ Wr,
                                const float* __restrict__ W1,
                                const float* __restrict__ b1,
                                const float* __restrict__ W2,
                                const float* __restrict__ b2,
                                float* __restrict__ out,
                                int m) {
    int i = blockIdx.x * blockDim.x + threadIdx.x;
    if (i >= m) return;

    float wl = __ldg(&Wl[0]);
    float wr = __ldg(&Wr[0]);
    float w10 = __ldg(&W1[0]), w11 = __ldg(&W1[1]);
    float bb0 = __ldg(&b1[0]), bb1 = __ldg(&b1[1]);
    float w20 = __ldg(&W2[0]), w21 = __ldg(&W2[1]);
    float bb2 = __ldg(&b2[0]);

    float h = g_agg[i] * wl + __ldg(&x[3 * i]) * wr;
    float a0 = fmaxf(fmaf(h, w10, bb0), 0.0f);
    float a1 = fmaxf(fmaf(h, w11, bb1), 0.0f);
    out[i] = fmaf(a0, w20, fmaf(a1, w21, bb2));
}

// ---------------------------------------------------------------------------
// Launch
// Inputs (metadata order): x[N,1] f32, edge_index[2,E] int32 (downcast from
// int64), W_l[1,1], W_r[1,1], W1[2,1], b1[2], W2[1,2], b2[1]
// Output: float[N/3]
// ---------------------------------------------------------------------------
extern "C" void kernel_launch(void* const* d_in, const int* in_sizes, int n_in,
                              void* d_out, int out_size) {
    const float* x  = (const float*)d_in[0];
    const int* edge_index = (const int*)d_in[1];
    const float* Wl = (const float*)d_in[2];
    const float* Wr = (const float*)d_in[3];
    const float* W1 = (const float*)d_in[4];
    const float* b1 = (const float*)d_in[5];
    const float* W2 = (const float*)d_in[6];
    const float* b2 = (const float*)d_in[7];
    float* out = (float*)d_out;

    int nedges = in_sizes[1] / 2;   // E (edge_index has 2*E elements)
    int m = out_size;               // N/3 output nodes

    const int* src = edge_index;
    const int* dst = edge_index + nedges;

    // 1) zero scratch (m is 1,000,000 -> divisible by 4)
    int m4 = m / 4;
    zero_agg_kernel<<<(m4 + 255) / 256, 256>>>(m4);

    // 2) scatter: one thread per 4 edges
    int nquads = nedges >> 2;
    int blocks = (nquads + 255) / 256;
    scatter_kernel<<<blocks, 256>>>(src, dst, x, nedges);

    // 3) finalize
    finalize_kernel<<<(m + 255) / 256, 256>>>(x, Wl, Wr, W1, b1, W2, b2, out, m);
}